// round 4
// baseline (speedup 1.0000x reference)
#include <cuda_runtime.h>
#include <math.h>

#define NN   100000
#define EE   1600000
#define ENL  1700000     // edges + self loops
#define FIN  1024
#define F1   128         // H1*C1
#define H1   16
#define C1   8
#define C2   19
#define C2P  20          // padded row for layer-2 features

// ---------------- scratch (device globals; no allocation allowed) ----------------
__device__ float    g_h1   [(size_t)NN * F1];   // x @ W1
__device__ float    g_out1 [(size_t)NN * F1];   // layer-1 aggregated output (then ELU'd in place)
__device__ float    g_asrc1[NN * H1];
__device__ float    g_adst1[NN * H1];
__device__ unsigned g_amax1[NN * H1];
__device__ float    g_asum1[NN * H1];
__device__ float    g_h2   [NN * C2P];          // layer-2 features, col 19 = 0 pad
__device__ float    g_out2 [NN * C2P];
__device__ float    g_asrc2[NN];
__device__ float    g_adst2[NN];
__device__ unsigned g_amax2[NN];
__device__ float    g_asum2[NN];

// ---------------- helpers ----------------
__device__ __forceinline__ unsigned fenc(float f) {
    unsigned u = __float_as_uint(f);
    return (u & 0x80000000u) ? ~u : (u | 0x80000000u);
}
__device__ __forceinline__ float fdec(unsigned u) {
    return __uint_as_float((u & 0x80000000u) ? (u & 0x7fffffffu) : ~u);
}
__device__ __forceinline__ float lrelu(float x) { return x >= 0.f ? x : 0.2f * x; }

__device__ __forceinline__ void red4(float* p, float a, float b, float c, float d) {
    asm volatile("red.global.add.v4.f32 [%0], {%1,%2,%3,%4};"
                 :: "l"(p), "f"(a), "f"(b), "f"(c), "f"(d) : "memory");
}

__device__ __forceinline__ void edge_sd(const int* __restrict__ ei, int e, int& s, int& d) {
    if (e < EE) { s = ei[e]; d = ei[EE + e]; }
    else        { s = e - EE; d = s; }
}

// ---------------- init: zero accumulators ----------------
__global__ void k_init() {
    int tid = blockIdx.x * blockDim.x + threadIdx.x;
    int stride = gridDim.x * blockDim.x;
    for (int i = tid; i < NN * F1; i += stride) g_out1[i] = 0.f;
    for (int i = tid; i < NN * H1; i += stride) { g_amax1[i] = 0u; g_asum1[i] = 0.f; }
    for (int i = tid; i < NN * C2P; i += stride) g_out2[i] = 0.f;
    for (int i = tid; i < NN; i += stride) { g_amax2[i] = 0u; g_asum2[i] = 0.f; }
}

// ---------------- GEMM1: h1[NN,128] = x[NN,1024] @ W1[1024,128] ----------------
// 128x128x16 tile, 256 threads, 8x8 per-thread micro-tile.
__global__ __launch_bounds__(256, 2) void k_gemm1(const float* __restrict__ x,
                                                  const float* __restrict__ W) {
    __shared__ __align__(16) float As[16][132];   // [k][m], transposed on store
    __shared__ __align__(16) float Bs[16][132];   // [k][n]
    const int t  = threadIdx.x;
    const int tx = t & 15, ty = t >> 4;
    const int row0 = blockIdx.x * 128;
    const int mA = t >> 2, k4 = t & 3;       // A-load: (row mA / mA+64, 4 cols at k4*4)
    const int kB = t >> 5, n4 = t & 31;      // B-load: (row kB / kB+8, 4 cols at n4*4)

    float acc[8][8];
#pragma unroll
    for (int i = 0; i < 8; i++)
#pragma unroll
        for (int j = 0; j < 8; j++) acc[i][j] = 0.f;

    const int r0 = row0 + mA, r1 = row0 + mA + 64;

    for (int kt = 0; kt < FIN / 16; kt++) {
        float4 a0 = make_float4(0.f, 0.f, 0.f, 0.f), a1 = a0;
        if (r0 < NN) a0 = *(const float4*)&x[(size_t)r0 * FIN + kt * 16 + k4 * 4];
        if (r1 < NN) a1 = *(const float4*)&x[(size_t)r1 * FIN + kt * 16 + k4 * 4];
        float4 b0 = *(const float4*)&W[(size_t)(kt * 16 + kB) * F1 + n4 * 4];
        float4 b1 = *(const float4*)&W[(size_t)(kt * 16 + kB + 8) * F1 + n4 * 4];

        __syncthreads();
        As[k4 * 4 + 0][mA] = a0.x; As[k4 * 4 + 1][mA] = a0.y;
        As[k4 * 4 + 2][mA] = a0.z; As[k4 * 4 + 3][mA] = a0.w;
        As[k4 * 4 + 0][mA + 64] = a1.x; As[k4 * 4 + 1][mA + 64] = a1.y;
        As[k4 * 4 + 2][mA + 64] = a1.z; As[k4 * 4 + 3][mA + 64] = a1.w;
        *(float4*)&Bs[kB][n4 * 4]     = b0;
        *(float4*)&Bs[kB + 8][n4 * 4] = b1;
        __syncthreads();

#pragma unroll
        for (int k = 0; k < 16; k++) {
            float a[8], b[8];
            *(float4*)&a[0] = *(const float4*)&As[k][ty * 8];
            *(float4*)&a[4] = *(const float4*)&As[k][ty * 8 + 4];
            *(float4*)&b[0] = *(const float4*)&Bs[k][tx * 8];
            *(float4*)&b[4] = *(const float4*)&Bs[k][tx * 8 + 4];
#pragma unroll
            for (int i = 0; i < 8; i++)
#pragma unroll
                for (int j = 0; j < 8; j++) acc[i][j] += a[i] * b[j];
        }
    }

#pragma unroll
    for (int i = 0; i < 8; i++) {
        int r = row0 + ty * 8 + i;
        if (r < NN) {
            *(float4*)&g_h1[(size_t)r * F1 + tx * 8]     = make_float4(acc[i][0], acc[i][1], acc[i][2], acc[i][3]);
            *(float4*)&g_h1[(size_t)r * F1 + tx * 8 + 4] = make_float4(acc[i][4], acc[i][5], acc[i][6], acc[i][7]);
        }
    }
}

// ---------------- attention projections layer 1 (warp per node) ----------------
__global__ void k_attproj1(const float* __restrict__ att_s, const float* __restrict__ att_d) {
    int warp = (blockIdx.x * blockDim.x + threadIdx.x) >> 5;
    int lane = threadIdx.x & 31;
    if (warp >= NN) return;
    float4 v  = *(const float4*)&g_h1[(size_t)warp * F1 + lane * 4];
    float4 as = *(const float4*)&att_s[lane * 4];
    float4 ad = *(const float4*)&att_d[lane * 4];
    float ps = v.x * as.x + v.y * as.y + v.z * as.z + v.w * as.w;
    float pd = v.x * ad.x + v.y * ad.y + v.z * ad.z + v.w * ad.w;
    ps += __shfl_xor_sync(0xffffffffu, ps, 1);
    pd += __shfl_xor_sync(0xffffffffu, pd, 1);
    if (!(lane & 1)) {
        g_asrc1[warp * H1 + (lane >> 1)] = ps;
        g_adst1[warp * H1 + (lane >> 1)] = pd;
    }
}

// ---------------- layer-1 edge passes ----------------
__global__ void k_edge_max1(const int* __restrict__ ei) {
    int e = blockIdx.x * blockDim.x + threadIdx.x;
    if (e >= ENL) return;
    int s, d; edge_sd(ei, e, s, d);
    float sv[16], dv[16];
#pragma unroll
    for (int i = 0; i < 4; i++) {
        *(float4*)&sv[i * 4] = *(const float4*)&g_asrc1[s * H1 + i * 4];
        *(float4*)&dv[i * 4] = *(const float4*)&g_adst1[d * H1 + i * 4];
    }
#pragma unroll
    for (int h = 0; h < 16; h++)
        atomicMax(&g_amax1[d * H1 + h], fenc(lrelu(sv[h] + dv[h])));
}

__global__ void k_edge_sum1(const int* __restrict__ ei) {
    int e = blockIdx.x * blockDim.x + threadIdx.x;
    if (e >= ENL) return;
    int s, d; edge_sd(ei, e, s, d);
    float sv[16], dv[16];
#pragma unroll
    for (int i = 0; i < 4; i++) {
        *(float4*)&sv[i * 4] = *(const float4*)&g_asrc1[s * H1 + i * 4];
        *(float4*)&dv[i * 4] = *(const float4*)&g_adst1[d * H1 + i * 4];
    }
#pragma unroll
    for (int h = 0; h < 16; h++) {
        float al = lrelu(sv[h] + dv[h]);
        float m  = fdec(g_amax1[d * H1 + h]);
        atomicAdd(&g_asum1[d * H1 + h], expf(al - m));
    }
}

// one thread per (edge, head)
__global__ void k_edge_agg1(const int* __restrict__ ei) {
    int t = blockIdx.x * blockDim.x + threadIdx.x;
    if (t >= ENL * H1) return;
    int e = t >> 4, h = t & 15;
    int s, d; edge_sd(ei, e, s, d);
    float al = lrelu(g_asrc1[s * H1 + h] + g_adst1[d * H1 + h]);
    float m  = fdec(g_amax1[d * H1 + h]);
    float w  = expf(al - m) / (g_asum1[d * H1 + h] + 1e-16f);
    const float4* hp = (const float4*)&g_h1[(size_t)s * F1 + h * 8];
    float4 v0 = hp[0], v1 = hp[1];
    float* op = &g_out1[(size_t)d * F1 + h * 8];
    red4(op,     v0.x * w, v0.y * w, v0.z * w, v0.w * w);
    red4(op + 4, v1.x * w, v1.y * w, v1.z * w, v1.w * w);
}

// ---------------- ELU (+bias) in place ----------------
__global__ void k_elu(const float* __restrict__ b1) {
    int i = blockIdx.x * blockDim.x + threadIdx.x;
    if (i >= NN * F1) return;
    float v = g_out1[i] + b1[i & 127];
    g_out1[i] = v > 0.f ? v : expm1f(v);
}

// ---------------- GEMM2 + attention projections layer 2 (warp per node) ----------------
__global__ __launch_bounds__(256) void k_gemm2(const float* __restrict__ W2,
                                               const float* __restrict__ as2,
                                               const float* __restrict__ ad2) {
    __shared__ __align__(16) float sW[C2][F1];   // transposed: sW[j][k]
    int tid = threadIdx.x;
    for (int idx = tid; idx < F1 * C2; idx += 256) {
        int k = idx / C2, j = idx % C2;
        sW[j][k] = W2[idx];
    }
    __syncthreads();

    int n = blockIdx.x * 8 + (tid >> 5);
    int lane = tid & 31;
    if (n >= NN) return;

    float4 a = *(const float4*)&g_out1[(size_t)n * F1 + lane * 4];
    float mine = 0.f;
#pragma unroll
    for (int j = 0; j < C2; j++) {
        float4 w = *(const float4*)&sW[j][lane * 4];
        float p = a.x * w.x + a.y * w.y + a.z * w.z + a.w * w.w;
#pragma unroll
        for (int o = 16; o; o >>= 1) p += __shfl_xor_sync(0xffffffffu, p, o);
        if (lane == j) mine = p;
    }
    if (lane < C2P) g_h2[n * C2P + lane] = (lane < C2) ? mine : 0.f;

    float psrc = (lane < C2) ? mine * as2[lane] : 0.f;
    float pdst = (lane < C2) ? mine * ad2[lane] : 0.f;
#pragma unroll
    for (int o = 16; o; o >>= 1) {
        psrc += __shfl_xor_sync(0xffffffffu, psrc, o);
        pdst += __shfl_xor_sync(0xffffffffu, pdst, o);
    }
    if (lane == 0) { g_asrc2[n] = psrc; g_adst2[n] = pdst; }
}

// ---------------- layer-2 edge passes (H=1) ----------------
__global__ void k_edge_max2(const int* __restrict__ ei) {
    int e = blockIdx.x * blockDim.x + threadIdx.x;
    if (e >= ENL) return;
    int s, d; edge_sd(ei, e, s, d);
    atomicMax(&g_amax2[d], fenc(lrelu(g_asrc2[s] + g_adst2[d])));
}

__global__ void k_edge_sum2(const int* __restrict__ ei) {
    int e = blockIdx.x * blockDim.x + threadIdx.x;
    if (e >= ENL) return;
    int s, d; edge_sd(ei, e, s, d);
    float al = lrelu(g_asrc2[s] + g_adst2[d]);
    atomicAdd(&g_asum2[d], expf(al - fdec(g_amax2[d])));
}

__global__ void k_edge_agg2(const int* __restrict__ ei) {
    int e = blockIdx.x * blockDim.x + threadIdx.x;
    if (e >= ENL) return;
    int s, d; edge_sd(ei, e, s, d);
    float al = lrelu(g_asrc2[s] + g_adst2[d]);
    float w  = expf(al - fdec(g_amax2[d])) / (g_asum2[d] + 1e-16f);
    const float4* hp = (const float4*)&g_h2[s * C2P];
    float* op = &g_out2[d * C2P];
#pragma unroll
    for (int i = 0; i < 5; i++) {
        float4 v = hp[i];
        red4(op + i * 4, v.x * w, v.y * w, v.z * w, v.w * w);
    }
}

// ---------------- final: bias + log_softmax over 19 classes ----------------
__global__ void k_final(const float* __restrict__ b2, float* __restrict__ out) {
    int n = blockIdx.x * blockDim.x + threadIdx.x;
    if (n >= NN) return;
    float v[C2];
    float m = -1e30f;
#pragma unroll
    for (int j = 0; j < C2; j++) {
        v[j] = g_out2[n * C2P + j] + b2[j];
        m = fmaxf(m, v[j]);
    }
    float ssum = 0.f;
#pragma unroll
    for (int j = 0; j < C2; j++) ssum += expf(v[j] - m);
    float l = m + logf(ssum);
#pragma unroll
    for (int j = 0; j < C2; j++) out[n * C2 + j] = v[j] - l;
}

// ---------------- launch ----------------
extern "C" void kernel_launch(void* const* d_in, const int* in_sizes, int n_in,
                              void* d_out, int out_size) {
    const float* x   = (const float*)d_in[0];
    const int*   ei  = (const int*)  d_in[1];
    const float* W1  = (const float*)d_in[2];
    const float* as1 = (const float*)d_in[3];
    const float* ad1 = (const float*)d_in[4];
    const float* b1  = (const float*)d_in[5];
    const float* W2  = (const float*)d_in[6];
    const float* as2 = (const float*)d_in[7];
    const float* ad2 = (const float*)d_in[8];
    const float* b2  = (const float*)d_in[9];
    float* out = (float*)d_out;

    k_init<<<4096, 256>>>();
    k_gemm1<<<(NN + 127) / 128, 256>>>(x, W1);
    k_attproj1<<<(NN + 7) / 8, 256>>>(as1, ad1);
    k_edge_max1<<<(ENL + 255) / 256, 256>>>(ei);
    k_edge_sum1<<<(ENL + 255) / 256, 256>>>(ei);
    k_edge_agg1<<<(ENL * H1 + 255) / 256, 256>>>(ei);
    k_elu<<<(NN * F1 + 255) / 256, 256>>>(b1);
    k_gemm2<<<(NN + 7) / 8, 256>>>(W2, as2, ad2);
    k_edge_max2<<<(ENL + 255) / 256, 256>>>(ei);
    k_edge_sum2<<<(ENL + 255) / 256, 256>>>(ei);
    k_edge_agg2<<<(ENL + 255) / 256, 256>>>(ei);
    k_final<<<(NN + 255) / 256, 256>>>(b2, out);
}

// round 5
// speedup vs baseline: 1.0013x; 1.0013x over previous
#include <cuda_runtime.h>
#include <math.h>

#define NN   100000
#define EE   1600000
#define ENL  1700000     // edges + self loops
#define FIN  1024
#define F1   128         // H1*C1
#define H1   16
#define C1   8
#define C2   19
#define C2P  20          // padded row for layer-2 features

// ---------------- scratch (device globals; no allocation allowed) ----------------
__device__ float    g_h1   [(size_t)NN * F1];   // x @ W1
__device__ float    g_out1 [(size_t)NN * F1];   // layer-1 aggregated output (then ELU'd in place)
__device__ float    g_asrc1[NN * H1];
__device__ float    g_adst1[NN * H1];
__device__ unsigned g_amax1[NN * H1];
__device__ float    g_asum1[NN * H1];
__device__ float    g_h2   [NN * C2P];          // layer-2 features, col 19 = 0 pad
__device__ float    g_out2 [NN * C2P];
__device__ float    g_asrc2[NN];
__device__ float    g_adst2[NN];
__device__ unsigned g_amax2[NN];
__device__ float    g_asum2[NN];

// ---------------- helpers ----------------
__device__ __forceinline__ unsigned fenc(float f) {
    unsigned u = __float_as_uint(f);
    return (u & 0x80000000u) ? ~u : (u | 0x80000000u);
}
__device__ __forceinline__ float fdec(unsigned u) {
    return __uint_as_float((u & 0x80000000u) ? (u & 0x7fffffffu) : ~u);
}
__device__ __forceinline__ float lrelu(float x) { return x >= 0.f ? x : 0.2f * x; }

__device__ __forceinline__ void red4(float* p, float a, float b, float c, float d) {
    asm volatile("red.global.add.v4.f32 [%0], {%1,%2,%3,%4};"
                 :: "l"(p), "f"(a), "f"(b), "f"(c), "f"(d) : "memory");
}

__device__ __forceinline__ void edge_sd(const int* __restrict__ ei, int e, int& s, int& d) {
    if (e < EE) { s = ei[e]; d = ei[EE + e]; }
    else        { s = e - EE; d = s; }
}

// ---------------- init: zero accumulators ----------------
__global__ void k_init() {
    int tid = blockIdx.x * blockDim.x + threadIdx.x;
    int stride = gridDim.x * blockDim.x;
    for (int i = tid; i < NN * F1; i += stride) g_out1[i] = 0.f;
    for (int i = tid; i < NN * H1; i += stride) { g_amax1[i] = 0u; g_asum1[i] = 0.f; }
    for (int i = tid; i < NN * C2P; i += stride) g_out2[i] = 0.f;
    for (int i = tid; i < NN; i += stride) { g_amax2[i] = 0u; g_asum2[i] = 0.f; }
}

// ---------------- GEMM1: h1[NN,128] = x[NN,1024] @ W1[1024,128] ----------------
// 128x128x16 tile, 256 threads, 8x8 per-thread micro-tile.
__global__ __launch_bounds__(256, 2) void k_gemm1(const float* __restrict__ x,
                                                  const float* __restrict__ W) {
    __shared__ __align__(16) float As[16][132];   // [k][m], transposed on store
    __shared__ __align__(16) float Bs[16][132];   // [k][n]
    const int t  = threadIdx.x;
    const int tx = t & 15, ty = t >> 4;
    const int row0 = blockIdx.x * 128;
    const int mA = t >> 2, k4 = t & 3;       // A-load: (row mA / mA+64, 4 cols at k4*4)
    const int kB = t >> 5, n4 = t & 31;      // B-load: (row kB / kB+8, 4 cols at n4*4)

    float acc[8][8];
#pragma unroll
    for (int i = 0; i < 8; i++)
#pragma unroll
        for (int j = 0; j < 8; j++) acc[i][j] = 0.f;

    const int r0 = row0 + mA, r1 = row0 + mA + 64;

    for (int kt = 0; kt < FIN / 16; kt++) {
        float4 a0 = make_float4(0.f, 0.f, 0.f, 0.f), a1 = a0;
        if (r0 < NN) a0 = *(const float4*)&x[(size_t)r0 * FIN + kt * 16 + k4 * 4];
        if (r1 < NN) a1 = *(const float4*)&x[(size_t)r1 * FIN + kt * 16 + k4 * 4];
        float4 b0 = *(const float4*)&W[(size_t)(kt * 16 + kB) * F1 + n4 * 4];
        float4 b1 = *(const float4*)&W[(size_t)(kt * 16 + kB + 8) * F1 + n4 * 4];

        __syncthreads();
        As[k4 * 4 + 0][mA] = a0.x; As[k4 * 4 + 1][mA] = a0.y;
        As[k4 * 4 + 2][mA] = a0.z; As[k4 * 4 + 3][mA] = a0.w;
        As[k4 * 4 + 0][mA + 64] = a1.x; As[k4 * 4 + 1][mA + 64] = a1.y;
        As[k4 * 4 + 2][mA + 64] = a1.z; As[k4 * 4 + 3][mA + 64] = a1.w;
        *(float4*)&Bs[kB][n4 * 4]     = b0;
        *(float4*)&Bs[kB + 8][n4 * 4] = b1;
        __syncthreads();

#pragma unroll
        for (int k = 0; k < 16; k++) {
            float a[8], b[8];
            *(float4*)&a[0] = *(const float4*)&As[k][ty * 8];
            *(float4*)&a[4] = *(const float4*)&As[k][ty * 8 + 4];
            *(float4*)&b[0] = *(const float4*)&Bs[k][tx * 8];
            *(float4*)&b[4] = *(const float4*)&Bs[k][tx * 8 + 4];
#pragma unroll
            for (int i = 0; i < 8; i++)
#pragma unroll
                for (int j = 0; j < 8; j++) acc[i][j] += a[i] * b[j];
        }
    }

#pragma unroll
    for (int i = 0; i < 8; i++) {
        int r = row0 + ty * 8 + i;
        if (r < NN) {
            *(float4*)&g_h1[(size_t)r * F1 + tx * 8]     = make_float4(acc[i][0], acc[i][1], acc[i][2], acc[i][3]);
            *(float4*)&g_h1[(size_t)r * F1 + tx * 8 + 4] = make_float4(acc[i][4], acc[i][5], acc[i][6], acc[i][7]);
        }
    }
}

// ---------------- attention projections layer 1 (warp per node) ----------------
__global__ void k_attproj1(const float* __restrict__ att_s, const float* __restrict__ att_d) {
    int warp = (blockIdx.x * blockDim.x + threadIdx.x) >> 5;
    int lane = threadIdx.x & 31;
    if (warp >= NN) return;
    float4 v  = *(const float4*)&g_h1[(size_t)warp * F1 + lane * 4];
    float4 as = *(const float4*)&att_s[lane * 4];
    float4 ad = *(const float4*)&att_d[lane * 4];
    float ps = v.x * as.x + v.y * as.y + v.z * as.z + v.w * as.w;
    float pd = v.x * ad.x + v.y * ad.y + v.z * ad.z + v.w * ad.w;
    ps += __shfl_xor_sync(0xffffffffu, ps, 1);
    pd += __shfl_xor_sync(0xffffffffu, pd, 1);
    if (!(lane & 1)) {
        g_asrc1[warp * H1 + (lane >> 1)] = ps;
        g_adst1[warp * H1 + (lane >> 1)] = pd;
    }
}

// ---------------- layer-1 edge passes ----------------
__global__ void k_edge_max1(const int* __restrict__ ei) {
    int e = blockIdx.x * blockDim.x + threadIdx.x;
    if (e >= ENL) return;
    int s, d; edge_sd(ei, e, s, d);
    float sv[16], dv[16];
#pragma unroll
    for (int i = 0; i < 4; i++) {
        *(float4*)&sv[i * 4] = *(const float4*)&g_asrc1[s * H1 + i * 4];
        *(float4*)&dv[i * 4] = *(const float4*)&g_adst1[d * H1 + i * 4];
    }
#pragma unroll
    for (int h = 0; h < 16; h++)
        atomicMax(&g_amax1[d * H1 + h], fenc(lrelu(sv[h] + dv[h])));
}

__global__ void k_edge_sum1(const int* __restrict__ ei) {
    int e = blockIdx.x * blockDim.x + threadIdx.x;
    if (e >= ENL) return;
    int s, d; edge_sd(ei, e, s, d);
    float sv[16], dv[16];
#pragma unroll
    for (int i = 0; i < 4; i++) {
        *(float4*)&sv[i * 4] = *(const float4*)&g_asrc1[s * H1 + i * 4];
        *(float4*)&dv[i * 4] = *(const float4*)&g_adst1[d * H1 + i * 4];
    }
#pragma unroll
    for (int h = 0; h < 16; h++) {
        float al = lrelu(sv[h] + dv[h]);
        float m  = fdec(g_amax1[d * H1 + h]);
        atomicAdd(&g_asum1[d * H1 + h], expf(al - m));
    }
}

// one thread per (edge, head)
__global__ void k_edge_agg1(const int* __restrict__ ei) {
    int t = blockIdx.x * blockDim.x + threadIdx.x;
    if (t >= ENL * H1) return;
    int e = t >> 4, h = t & 15;
    int s, d; edge_sd(ei, e, s, d);
    float al = lrelu(g_asrc1[s * H1 + h] + g_adst1[d * H1 + h]);
    float m  = fdec(g_amax1[d * H1 + h]);
    float w  = expf(al - m) / (g_asum1[d * H1 + h] + 1e-16f);
    const float4* hp = (const float4*)&g_h1[(size_t)s * F1 + h * 8];
    float4 v0 = hp[0], v1 = hp[1];
    float* op = &g_out1[(size_t)d * F1 + h * 8];
    red4(op,     v0.x * w, v0.y * w, v0.z * w, v0.w * w);
    red4(op + 4, v1.x * w, v1.y * w, v1.z * w, v1.w * w);
}

// ---------------- ELU (+bias) in place ----------------
__global__ void k_elu(const float* __restrict__ b1) {
    int i = blockIdx.x * blockDim.x + threadIdx.x;
    if (i >= NN * F1) return;
    float v = g_out1[i] + b1[i & 127];
    g_out1[i] = v > 0.f ? v : expm1f(v);
}

// ---------------- GEMM2 + attention projections layer 2 (warp per node) ----------------
__global__ __launch_bounds__(256) void k_gemm2(const float* __restrict__ W2,
                                               const float* __restrict__ as2,
                                               const float* __restrict__ ad2) {
    __shared__ __align__(16) float sW[C2][F1];   // transposed: sW[j][k]
    int tid = threadIdx.x;
    for (int idx = tid; idx < F1 * C2; idx += 256) {
        int k = idx / C2, j = idx % C2;
        sW[j][k] = W2[idx];
    }
    __syncthreads();

    int n = blockIdx.x * 8 + (tid >> 5);
    int lane = tid & 31;
    if (n >= NN) return;

    float4 a = *(const float4*)&g_out1[(size_t)n * F1 + lane * 4];
    float mine = 0.f;
#pragma unroll
    for (int j = 0; j < C2; j++) {
        float4 w = *(const float4*)&sW[j][lane * 4];
        float p = a.x * w.x + a.y * w.y + a.z * w.z + a.w * w.w;
#pragma unroll
        for (int o = 16; o; o >>= 1) p += __shfl_xor_sync(0xffffffffu, p, o);
        if (lane == j) mine = p;
    }
    if (lane < C2P) g_h2[n * C2P + lane] = (lane < C2) ? mine : 0.f;

    float psrc = (lane < C2) ? mine * as2[lane] : 0.f;
    float pdst = (lane < C2) ? mine * ad2[lane] : 0.f;
#pragma unroll
    for (int o = 16; o; o >>= 1) {
        psrc += __shfl_xor_sync(0xffffffffu, psrc, o);
        pdst += __shfl_xor_sync(0xffffffffu, pdst, o);
    }
    if (lane == 0) { g_asrc2[n] = psrc; g_adst2[n] = pdst; }
}

// ---------------- layer-2 edge passes (H=1) ----------------
__global__ void k_edge_max2(const int* __restrict__ ei) {
    int e = blockIdx.x * blockDim.x + threadIdx.x;
    if (e >= ENL) return;
    int s, d; edge_sd(ei, e, s, d);
    atomicMax(&g_amax2[d], fenc(lrelu(g_asrc2[s] + g_adst2[d])));
}

__global__ void k_edge_sum2(const int* __restrict__ ei) {
    int e = blockIdx.x * blockDim.x + threadIdx.x;
    if (e >= ENL) return;
    int s, d; edge_sd(ei, e, s, d);
    float al = lrelu(g_asrc2[s] + g_adst2[d]);
    atomicAdd(&g_asum2[d], expf(al - fdec(g_amax2[d])));
}

__global__ void k_edge_agg2(const int* __restrict__ ei) {
    int e = blockIdx.x * blockDim.x + threadIdx.x;
    if (e >= ENL) return;
    int s, d; edge_sd(ei, e, s, d);
    float al = lrelu(g_asrc2[s] + g_adst2[d]);
    float w  = expf(al - fdec(g_amax2[d])) / (g_asum2[d] + 1e-16f);
    const float4* hp = (const float4*)&g_h2[s * C2P];
    float* op = &g_out2[d * C2P];
#pragma unroll
    for (int i = 0; i < 5; i++) {
        float4 v = hp[i];
        red4(op + i * 4, v.x * w, v.y * w, v.z * w, v.w * w);
    }
}

// ---------------- final: bias + log_softmax over 19 classes ----------------
__global__ void k_final(const float* __restrict__ b2, float* __restrict__ out) {
    int n = blockIdx.x * blockDim.x + threadIdx.x;
    if (n >= NN) return;
    float v[C2];
    float m = -1e30f;
#pragma unroll
    for (int j = 0; j < C2; j++) {
        v[j] = g_out2[n * C2P + j] + b2[j];
        m = fmaxf(m, v[j]);
    }
    float ssum = 0.f;
#pragma unroll
    for (int j = 0; j < C2; j++) ssum += expf(v[j] - m);
    float l = m + logf(ssum);
#pragma unroll
    for (int j = 0; j < C2; j++) out[n * C2 + j] = v[j] - l;
}

// ---------------- launch ----------------
extern "C" void kernel_launch(void* const* d_in, const int* in_sizes, int n_in,
                              void* d_out, int out_size) {
    const float* x   = (const float*)d_in[0];
    const int*   ei  = (const int*)  d_in[1];
    const float* W1  = (const float*)d_in[2];
    const float* as1 = (const float*)d_in[3];
    const float* ad1 = (const float*)d_in[4];
    const float* b1  = (const float*)d_in[5];
    const float* W2  = (const float*)d_in[6];
    const float* as2 = (const float*)d_in[7];
    const float* ad2 = (const float*)d_in[8];
    const float* b2  = (const float*)d_in[9];
    float* out = (float*)d_out;

    k_init<<<4096, 256>>>();
    k_gemm1<<<(NN + 127) / 128, 256>>>(x, W1);
    k_attproj1<<<(NN + 7) / 8, 256>>>(as1, ad1);
    k_edge_max1<<<(ENL + 255) / 256, 256>>>(ei);
    k_edge_sum1<<<(ENL + 255) / 256, 256>>>(ei);
    k_edge_agg1<<<(ENL * H1 + 255) / 256, 256>>>(ei);
    k_elu<<<(NN * F1 + 255) / 256, 256>>>(b1);
    k_gemm2<<<(NN + 7) / 8, 256>>>(W2, as2, ad2);
    k_edge_max2<<<(ENL + 255) / 256, 256>>>(ei);
    k_edge_sum2<<<(ENL + 255) / 256, 256>>>(ei);
    k_edge_agg2<<<(ENL + 255) / 256, 256>>>(ei);
    k_final<<<(NN + 255) / 256, 256>>>(b2, out);
}